// round 1
// baseline (speedup 1.0000x reference)
#include <cuda_runtime.h>

// Problem constants: B=4, C=64, D=16, H=64, W=64, C8=8, k=38 (top-k ratio 0.6)
#define EPSBN 1e-5f
#define NB 4
#define NC 64
#define ND 16
#define NH 64
#define NW 64
#define NDHW (ND*NH*NW)        // 65536
#define NTOT (NB*NC*NDHW)      // 16777216
#define NLOC (NB*NDHW)         // 262144

struct GParams {
  float wdw[NC*25];   // depthwise weights with bn1 scale folded in
  float t1[NC];       // bn1 bias term
  float w1t[NC*8];    // pw1 weights, [c][o] layout, bn2 scale folded
  float b1[8];        // pw1 bias with bn2 folded
  float w2[NC*8];     // pw2 weights [c][o]
  float b2c[NC];      // pw2 bias
  float alpha;
};

__device__   GParams g_gp;       // written by prep kernel
__constant__ GParams c_gp;       // uniform-path copy for hot kernels
__device__   float   g_y1[NTOT]; // scratch: silu(bn1(dwconv(x)))

__device__ __forceinline__ float silu_f(float v) {
  return v * (1.0f / (1.0f + __expf(-v)));
}

// ---------------------------------------------------------------------------
// Prep: fold BN params into weights (one tiny block)
// ---------------------------------------------------------------------------
__global__ void kprep(const float* __restrict__ wdw,
                      const float* __restrict__ g1, const float* __restrict__ be1,
                      const float* __restrict__ m1, const float* __restrict__ v1,
                      const float* __restrict__ wp1, const float* __restrict__ bp1,
                      const float* __restrict__ g2, const float* __restrict__ be2,
                      const float* __restrict__ m2, const float* __restrict__ v2,
                      const float* __restrict__ wp2, const float* __restrict__ bp2,
                      const float* __restrict__ alpha) {
  int c = threadIdx.x;
  if (c < NC) {
    float s1 = g1[c] * rsqrtf(v1[c] + EPSBN);
    #pragma unroll
    for (int j = 0; j < 25; j++) g_gp.wdw[c*25+j] = wdw[c*25+j] * s1;
    g_gp.t1[c] = be1[c] - m1[c] * s1;
    #pragma unroll
    for (int o = 0; o < 8; o++) {
      float s2 = g2[o] * rsqrtf(v2[o] + EPSBN);
      g_gp.w1t[c*8+o] = wp1[o*NC+c] * s2;
      g_gp.w2[c*8+o]  = wp2[c*8+o];
    }
    g_gp.b2c[c] = bp2[c];
    if (c < 8) {
      float s2 = g2[c] * rsqrtf(v2[c] + EPSBN);
      g_gp.b1[c] = (bp1[c] - m2[c]) * s2 + be2[c];
    }
    if (c == 0) g_gp.alpha = alpha[0];
  }
}

// ---------------------------------------------------------------------------
// Kernel 1: depthwise (1,5,5) conv + BN + SiLU -> g_y1
// One block per (b,c,d) 64x64 plane. Plane cached in smem with halo.
// Each thread produces 4 w-consecutive outputs in 4 separate rows
// (2x float4 LDS per tap row -> ~10 smem floats per output).
// ---------------------------------------------------------------------------
#define T1ROWS 68          // 64 + 2*2 halo rows
#define T1PITCH 72         // padded cols: col index = w + 2, 16B-aligned rows
__global__ void __launch_bounds__(256) k_dwconv(const float* __restrict__ x) {
  __shared__ float tile[T1ROWS * T1PITCH];
  int p = blockIdx.x;                  // ((b*C + c)*D + d), 0..4095
  int c = (p >> 4) & 63;
  const float* xp = x + (size_t)p * (NH * NW);
  int tid = threadIdx.x;

  // zero (halo), then load interior
  for (int i = tid; i < T1ROWS * T1PITCH; i += 256) tile[i] = 0.f;
  __syncthreads();
  for (int i = tid; i < (NH * NW) / 4; i += 256) {
    int h = i >> 4;
    int w4 = (i & 15) * 4;
    float4 v = *reinterpret_cast<const float4*>(xp + h * NW + w4);
    float* dst = &tile[(h + 2) * T1PITCH + (w4 + 2)];
    dst[0] = v.x; dst[1] = v.y; dst[2] = v.z; dst[3] = v.w;
  }
  __syncthreads();

  float wk[25];
  #pragma unroll
  for (int j = 0; j < 25; j++) wk[j] = c_gp.wdw[c*25 + j];
  float t1 = c_gp.t1[c];

  int wq = tid & 15;        // w group: outputs w = 4*wq .. 4*wq+3
  int hb = tid >> 4;        // row within 16-row stripe
  float* yp = g_y1 + (size_t)p * (NH * NW);

  #pragma unroll
  for (int g = 0; g < 4; g++) {
    int h = hb + g * 16;
    float a0 = 0.f, a1 = 0.f, a2 = 0.f, a3 = 0.f;
    #pragma unroll
    for (int r = 0; r < 5; r++) {
      // taps for outputs 4wq..4wq+3 span smem cols 4wq .. 4wq+7 (16B aligned)
      const float* row = &tile[(h + r) * T1PITCH + 4 * wq];
      float4 va = *reinterpret_cast<const float4*>(row);
      float4 vb = *reinterpret_cast<const float4*>(row + 4);
      float f0 = va.x, f1 = va.y, f2 = va.z, f3 = va.w;
      float f4 = vb.x, f5 = vb.y, f6 = vb.z, f7 = vb.w;
      const float* wr = &wk[r * 5];
      a0 = fmaf(wr[0], f0, fmaf(wr[1], f1, fmaf(wr[2], f2, fmaf(wr[3], f3, fmaf(wr[4], f4, a0)))));
      a1 = fmaf(wr[0], f1, fmaf(wr[1], f2, fmaf(wr[2], f3, fmaf(wr[3], f4, fmaf(wr[4], f5, a1)))));
      a2 = fmaf(wr[0], f2, fmaf(wr[1], f3, fmaf(wr[2], f4, fmaf(wr[3], f5, fmaf(wr[4], f6, a2)))));
      a3 = fmaf(wr[0], f3, fmaf(wr[1], f4, fmaf(wr[2], f5, fmaf(wr[3], f6, fmaf(wr[4], f7, a3)))));
    }
    float4 o;
    o.x = silu_f(a0 + t1);
    o.y = silu_f(a1 + t1);
    o.z = silu_f(a2 + t1);
    o.w = silu_f(a3 + t1);
    *reinterpret_cast<float4*>(yp + h * NW + 4 * wq) = o;
  }
}

// ---------------------------------------------------------------------------
// 64-element in-register bitonic sort, fully unrolled (672 CE -> 1344 FMNMX)
// ---------------------------------------------------------------------------
__device__ __forceinline__ void sort64(float* s) {
  #pragma unroll
  for (int k = 2; k <= 64; k <<= 1) {
    #pragma unroll
    for (int j = k >> 1; j > 0; j >>= 1) {
      #pragma unroll
      for (int i = 0; i < 64; i++) {
        int l = i ^ j;
        if (l > i) {
          float a = s[i], b = s[l];
          float lo = fminf(a, b), hi = fmaxf(a, b);
          if ((i & k) == 0) { s[i] = lo; s[l] = hi; }
          else              { s[i] = hi; s[l] = lo; }
        }
      }
    }
  }
}

// ---------------------------------------------------------------------------
// Kernel 2: pointwise branch + attn + channel top-38 threshold + output.
// One thread per spatial location (b,d,h,w); all 64 channels in registers.
// attn copies also parked in per-thread smem column (no recompute at output).
// ---------------------------------------------------------------------------
__global__ void __launch_bounds__(128) k_attn(const float* __restrict__ x,
                                              float* __restrict__ out) {
  __shared__ float sa[NC * 128];       // 32 KB: sa[c*128 + tid], private columns
  int tid = threadIdx.x;
  int t = blockIdx.x * 128 + tid;      // 0..262143
  int b = t >> 16;                     // t / DHW
  int sp = t & 65535;
  size_t base = (size_t)b * (NC * NDHW) + (size_t)sp;

  // pass 1: h[o] = b1_eff[o] + sum_c w1_eff[o,c] * x[c]
  float h[8];
  #pragma unroll
  for (int o = 0; o < 8; o++) h[o] = c_gp.b1[o];
  #pragma unroll
  for (int c = 0; c < NC; c++) {
    float xv = __ldg(x + base + (size_t)c * NDHW);
    #pragma unroll
    for (int o = 0; o < 8; o++) h[o] = fmaf(c_gp.w1t[c*8+o], xv, h[o]);
  }
  float hb[8];
  #pragma unroll
  for (int o = 0; o < 8; o++) hb[o] = silu_f(h[o]);

  // pass 2: attn[c] = y1[c] * (b2[c] + sum_o w2[c,o]*hb[o])
  float s[64];
  #pragma unroll
  for (int c = 0; c < NC; c++) {
    float y1v = __ldg(&g_y1[base + (size_t)c * NDHW]);
    float y2 = c_gp.b2c[c];
    #pragma unroll
    for (int o = 0; o < 8; o++) y2 = fmaf(c_gp.w2[c*8+o], hb[o], y2);
    float a = y1v * y2;
    sa[c * 128 + tid] = a;   // exact copy for output pass
    s[c] = a;
  }

  sort64(s);
  float thr = s[26];         // 38th largest of 64 (ascending index 64-38=26)
  float alpha = c_gp.alpha;

  // pass 3: out = x + alpha * attn * (attn >= thr)
  #pragma unroll 4
  for (int c = 0; c < NC; c++) {
    float a  = sa[c * 128 + tid];
    float xv = __ldg(x + base + (size_t)c * NDHW);
    float r  = (a >= thr) ? fmaf(alpha, a, xv) : xv;
    out[base + (size_t)c * NDHW] = r;
  }
}

// ---------------------------------------------------------------------------
extern "C" void kernel_launch(void* const* d_in, const int* in_sizes, int n_in,
                              void* d_out, int out_size) {
  const float* x    = (const float*)d_in[0];
  const float* wdw  = (const float*)d_in[1];
  const float* g1   = (const float*)d_in[2];
  const float* be1  = (const float*)d_in[3];
  const float* m1   = (const float*)d_in[4];
  const float* v1   = (const float*)d_in[5];
  const float* wp1  = (const float*)d_in[6];
  const float* bp1  = (const float*)d_in[7];
  const float* g2   = (const float*)d_in[8];
  const float* be2  = (const float*)d_in[9];
  const float* m2   = (const float*)d_in[10];
  const float* v2   = (const float*)d_in[11];
  const float* wp2  = (const float*)d_in[12];
  const float* bp2  = (const float*)d_in[13];
  const float* alpha= (const float*)d_in[14];
  float* out = (float*)d_out;

  kprep<<<1, 64>>>(wdw, g1, be1, m1, v1, wp1, bp1, g2, be2, m2, v2, wp2, bp2, alpha);

  void* gp_addr = nullptr;
  cudaGetSymbolAddress(&gp_addr, g_gp);
  cudaMemcpyToSymbolAsync(c_gp, gp_addr, sizeof(GParams), 0,
                          cudaMemcpyDeviceToDevice, 0);

  k_dwconv<<<NB * NC * ND, 256>>>(x);      // 4096 blocks
  k_attn<<<NLOC / 128, 128>>>(x, out);     // 2048 blocks
}